// round 11
// baseline (speedup 1.0000x reference)
#include <cuda_runtime.h>
#include <cstdint>
#include <cstddef>

// Problem constants
#define BB 4
#define CC 256
#define HH 128
#define WWI 128
#define HW 16384          // H*W
#define NTOK 65536        // B*HW
#define SCALE_F 0.08838834764831843f   // (256/2)^-0.5
#define EPS_F 1e-4f

// Scratch (device globals — no allocations allowed)
__device__ float g_xc[(size_t)NTOK * CC];                 // attn+lepe out (PERM ch: branch*128+head*64+c)
// attention-layout tensors: [(branch*4+b)*32+wloc][head][j:512][c:64], tf32-rounded
// gQt/gKt have channels stored PAIR-INTERLEAVED: phys p holds channel chmap(p)
__device__ float gQt[(size_t)256 * 2 * 512 * 64];         // pre-scaled by SCALE
__device__ float gKt[(size_t)256 * 2 * 512 * 64];
__device__ float gVt[(size_t)256 * 2 * 512 * 64];         // identity channel order (lepe reads it)

// ---------------------------------------------------------------------------
__device__ __forceinline__ uint32_t f2tf(float f) {
    uint32_t u; asm("cvt.rna.tf32.f32 %0, %1;" : "=r"(u) : "f"(f)); return u;
}
__device__ __forceinline__ float f2tff(float f) { return __uint_as_float(f2tf(f)); }
__device__ __forceinline__ uint32_t fu(float f) { return __float_as_uint(f); }

// within-8 permutation: phys slot p holds logical index chmap(p); also used as
// the V row-staging remap (self-describing inverse pair with slotmap)
__device__ __forceinline__ int chmap(int p) {
    return (p & ~7) + ((p & 1) << 2) + ((p >> 1) & 3);
}

__device__ __forceinline__ void mma8(float* d,
    uint32_t a0, uint32_t a1, uint32_t a2, uint32_t a3, uint32_t b0, uint32_t b1) {
    asm volatile(
        "mma.sync.aligned.m16n8k8.row.col.f32.tf32.tf32.f32 "
        "{%0,%1,%2,%3},{%4,%5,%6,%7},{%8,%9},{%0,%1,%2,%3};\n"
        : "+f"(d[0]), "+f"(d[1]), "+f"(d[2]), "+f"(d[3])
        : "r"(a0), "r"(a1), "r"(a2), "r"(a3), "r"(b0), "r"(b1));
}

__device__ __forceinline__ void cpa16(void* dst, const void* src) {
    uint32_t d = (uint32_t)__cvta_generic_to_shared(dst);
    asm volatile("cp.async.cg.shared.global [%0], [%1], 16;\n" :: "r"(d), "l"(src));
}
#define CP_COMMIT() asm volatile("cp.async.commit_group;\n" ::: "memory")
#define CP_WAIT1()  asm volatile("cp.async.wait_group 1;\n" ::: "memory")
#define CP_WAIT0()  asm volatile("cp.async.wait_group 0;\n" ::: "memory")

__device__ __forceinline__ int tok_to_L(int branch, int wloc, int j) {
    if (branch == 0) { int hs = j >> 2, ws = j & 3;    return hs * WWI + wloc * 4 + ws; }
    else             { int hs = j >> 7, ws = j & 127;  return (wloc * 4 + hs) * WWI + ws; }
}

// ---------------------------------------------------------------------------
// 1) QKV GEMM with FUSED LayerNorm (tf32 tensor cores).
//    grid (6,512): bn fastest -> x tile & stats L2-reused.
//    A-load reads x [B,C,HW] directly, normalizing on the fly.
__global__ void qkv_tc_kernel(const float* __restrict__ x,
                              const float* __restrict__ gam,
                              const float* __restrict__ bet,
                              const float* __restrict__ Bmat) {
    extern __shared__ float sh[];
    float* As = sh;                 // [128][20]
    float* Bs = sh + 128 * 20;      // [16][136]
    __shared__ float smu[128], srs[128], sg[256], sbe[256];

    int bm = blockIdx.y, bn = blockIdx.x;
    int tid = threadIdx.x, wid = tid >> 5, lane = tid & 31;
    int g = lane >> 2, t4 = lane & 3;
    int wm = (wid >> 2) * 64, wn = (wid & 3) * 32;

    int gtok = bm * 128;
    int b = gtok >> 14, tb = gtok & 16383;
    const float* xb = x + (size_t)b * CC * HW + tb;

    // gamma/beta to smem
    sg[tid] = gam[tid];
    sbe[tid] = bet[tid];

    // ---- LN stats: warp w handles 16 tokens, lane halves split channels
    {
        int tok = wid * 16 + (lane & 15), halfc = (lane >> 4) * 128;
        const float* xr = xb + tok + (size_t)halfc * HW;
        float s = 0.f, s2 = 0.f;
        #pragma unroll 8
        for (int c = 0; c < 128; c++) {
            float v = xr[(size_t)c * HW];
            s += v; s2 += v * v;
        }
        s  += __shfl_xor_sync(0xffffffffu, s, 16);
        s2 += __shfl_xor_sync(0xffffffffu, s2, 16);
        if ((lane >> 4) == 0) {
            float mu = s * (1.f / 256.f);
            smu[tok] = mu;
            srs[tok] = rsqrtf(s2 * (1.f / 256.f) - mu * mu + EPS_F);
        }
    }

    float acc[4][4][4];
    #pragma unroll
    for (int mt = 0; mt < 4; mt++)
        #pragma unroll
        for (int nt = 0; nt < 4; nt++)
            #pragma unroll
            for (int r = 0; r < 4; r++) acc[mt][nt][r] = 0.f;

    __syncthreads();

    int kc = tid >> 4, tg = tid & 15;        // A-load mapping
    for (int k0 = 0; k0 < 256; k0 += 16) {
        { // A: 16 ch x 128 tok from x, normalize, cvt tf32
            const float* xr = xb + (size_t)(k0 + kc) * HW + tg * 8;
            float gm = sg[k0 + kc], be = sbe[k0 + kc];
            float4 v0 = *(const float4*)xr, v1 = *(const float4*)(xr + 4);
            float val[8] = {v0.x, v0.y, v0.z, v0.w, v1.x, v1.y, v1.z, v1.w};
            #pragma unroll
            for (int i = 0; i < 8; i++) {
                int j = (i + tg) & 7;        // store-rotation: breaks bank conflicts
                int tok = tg * 8 + j;
                As[tok * 20 + kc] = f2tff((val[j] - smu[tok]) * srs[tok] * gm + be);
            }
        }
        { // B: 16 x 128
            int kr = tid >> 5, n4 = (tid & 31) * 4;
            #pragma unroll
            for (int p = 0; p < 2; p++) {
                float4 w = *(const float4*)(Bmat + (size_t)(k0 + kr + p * 8) * 768 + bn * 128 + n4);
                float* db = Bs + (kr + p * 8) * 136 + n4;
                db[0] = f2tff(w.x); db[1] = f2tff(w.y); db[2] = f2tff(w.z); db[3] = f2tff(w.w);
            }
        }
        __syncthreads();
        #pragma unroll
        for (int ks = 0; ks < 2; ks++) {
            uint32_t bf[4][2];
            #pragma unroll
            for (int nt = 0; nt < 4; nt++) {
                bf[nt][0] = fu(Bs[(ks * 8 + t4) * 136 + wn + nt * 8 + g]);
                bf[nt][1] = fu(Bs[(ks * 8 + t4 + 4) * 136 + wn + nt * 8 + g]);
            }
            #pragma unroll
            for (int mt = 0; mt < 4; mt++) {
                uint32_t a0 = fu(As[(wm + mt * 16 + g) * 20 + ks * 8 + t4]);
                uint32_t a1 = fu(As[(wm + mt * 16 + g + 8) * 20 + ks * 8 + t4]);
                uint32_t a2 = fu(As[(wm + mt * 16 + g) * 20 + ks * 8 + t4 + 4]);
                uint32_t a3 = fu(As[(wm + mt * 16 + g + 8) * 20 + ks * 8 + t4 + 4]);
                #pragma unroll
                for (int nt = 0; nt < 4; nt++)
                    mma8(acc[mt][nt], a0, a1, a2, a3, bf[nt][0], bf[nt][1]);
            }
        }
        __syncthreads();
    }
    // stage C to smem
    float* Cs = sh;  // [128][132]
    #pragma unroll
    for (int mt = 0; mt < 4; mt++)
        #pragma unroll
        for (int nt = 0; nt < 4; nt++) {
            int r = wm + mt * 16 + g, cl = wn + nt * 8 + 2 * t4;
            Cs[r * 132 + cl]           = acc[mt][nt][0];
            Cs[r * 132 + cl + 1]       = acc[mt][nt][1];
            Cs[(r + 8) * 132 + cl]     = acc[mt][nt][2];
            Cs[(r + 8) * 132 + cl + 1] = acc[mt][nt][3];
        }
    __syncthreads();
    int qkvt = bn >> 1, branch = bn & 1;
    float* dst = (qkvt == 0) ? gQt : ((qkvt == 1) ? gKt : gVt);
    float mul = (qkvt == 0) ? SCALE_F : 1.f;
    bool perm = (qkvt != 2);                 // Q,K pair-interleaved; V identity
    for (int e = tid; e < 4096; e += 256) {
        int tl = e >> 5, h = (e >> 4) & 1, c4 = (e & 15) * 4;
        int mg = bm * 128 + tl, L = mg & 16383;
        int row = L >> 7, colL = L & 127;
        int wloc, j;
        if (branch == 0) { wloc = colL >> 2; j = row * 4 + (colL & 3); }
        else             { wloc = row >> 2;  j = ((row & 3) << 7) + colL; }
        int slab = ((branch << 2) + b) * 32 + wloc;
        size_t off = (((size_t)(slab * 2 + h)) * 512 + j) * 64 + c4;
        const float* cs = Cs + tl * 132 + h;
        int c0 = perm ? chmap(c4 + 0) : c4 + 0;
        int c1 = perm ? chmap(c4 + 1) : c4 + 1;
        int c2 = perm ? chmap(c4 + 2) : c4 + 2;
        int c3 = perm ? chmap(c4 + 3) : c4 + 3;
        float4 o;
        o.x = f2tff(cs[2 * c0] * mul);
        o.y = f2tff(cs[2 * c1] * mul);
        o.z = f2tff(cs[2 * c2] * mul);
        o.w = f2tff(cs[2 * c3] * mul);
        *(float4*)(dst + off) = o;
    }
}

// ---------------------------------------------------------------------------
// 2) Flash attention (tf32 tensor cores). 4 warps, Q frags in regs,
//    cp.async double-buffered K/V. P stays in registers (V row-permuted).
__global__ void __launch_bounds__(128) attn_tc_kernel() {
    extern __shared__ float sh[];
    float* KsA = sh;                 // [2][64*68]
    float* VsA = sh + 2 * 4352;      // [2][64*72]  (rows sigma-permuted)

    int bid = blockIdx.x;
    int qt = bid & 7, head = (bid >> 3) & 1, win = (bid >> 4) & 127, branch = bid >> 11;
    int b = win >> 5, wloc = win & 31;
    int slab = ((branch << 2) + b) * 32 + wloc;
    size_t base = ((size_t)(slab * 2 + head)) * 512 * 64;

    int tid = threadIdx.x, wid = tid >> 5, lane = tid & 31;
    int g = lane >> 2, t4 = lane & 3;
    int qm = wid * 16;

    // -- stage Q tile into KsA[0], extract fragments (channels pair-interleaved:
    //    phys ks*8+2*t4 holds (a0's ch), +1 holds (a2's ch) -> float2 loads)
    for (int e = tid; e < 1024; e += 128) {
        int r = e >> 4, c4 = (e & 15) * 4;
        cpa16(KsA + r * 68 + c4, gQt + base + (size_t)(qt * 64 + r) * 64 + c4);
    }
    CP_COMMIT(); CP_WAIT0();
    __syncthreads();
    uint32_t qf[8][4];
    #pragma unroll
    for (int ks = 0; ks < 8; ks++) {
        float2 lo = *(const float2*)(KsA + (qm + g) * 68 + ks * 8 + 2 * t4);
        float2 hi = *(const float2*)(KsA + (qm + g + 8) * 68 + ks * 8 + 2 * t4);
        qf[ks][0] = fu(lo.x); qf[ks][2] = fu(lo.y);
        qf[ks][1] = fu(hi.x); qf[ks][3] = fu(hi.y);
    }
    __syncthreads();

    // -- prologue: stage kt=0,1 (V rows permuted by sigma = chmap)
    #pragma unroll 1
    for (int pkt = 0; pkt < 2; pkt++) {
        float* kd = KsA + pkt * 4352;
        float* vd = VsA + pkt * 4608;
        size_t so = base + (size_t)(pkt * 64) * 64;
        for (int e = tid; e < 1024; e += 128) {
            int r = e >> 4, c4 = (e & 15) * 4;
            cpa16(kd + r * 68 + c4, gKt + so + r * 64 + c4);
            cpa16(vd + chmap(r) * 72 + c4, gVt + so + r * 64 + c4);
        }
        CP_COMMIT();
    }

    float o[8][4];
    #pragma unroll
    for (int nt = 0; nt < 8; nt++)
        #pragma unroll
        for (int r = 0; r < 4; r++) o[nt][r] = 0.f;
    float m0 = -1e30f, m1 = -1e30f, l0 = 0.f, l1 = 0.f;

    #pragma unroll 1
    for (int kt = 0; kt < 8; kt++) {
        int cur = kt & 1;
        float* Ks = KsA + cur * 4352;
        float* Vs = VsA + cur * 4608;
        CP_WAIT1();
        __syncthreads();

        // S = Q K^T  (K pair-interleaved -> one LDS.64 per mma)
        float s[8][4];
        #pragma unroll
        for (int nt = 0; nt < 8; nt++)
            #pragma unroll
            for (int r = 0; r < 4; r++) s[nt][r] = 0.f;
        #pragma unroll
        for (int ks = 0; ks < 8; ks++) {
            #pragma unroll
            for (int nt = 0; nt < 8; nt++) {
                float2 bb = *(const float2*)(Ks + (nt * 8 + g) * 68 + ks * 8 + 2 * t4);
                mma8(s[nt], qf[ks][0], qf[ks][1], qf[ks][2], qf[ks][3], fu(bb.x), fu(bb.y));
            }
        }

        // online softmax (all in registers)
        float rm0 = -1e30f, rm1 = -1e30f;
        #pragma unroll
        for (int nt = 0; nt < 8; nt++) {
            rm0 = fmaxf(rm0, fmaxf(s[nt][0], s[nt][1]));
            rm1 = fmaxf(rm1, fmaxf(s[nt][2], s[nt][3]));
        }
        rm0 = fmaxf(rm0, __shfl_xor_sync(0xffffffffu, rm0, 1));
        rm0 = fmaxf(rm0, __shfl_xor_sync(0xffffffffu, rm0, 2));
        rm1 = fmaxf(rm1, __shfl_xor_sync(0xffffffffu, rm1, 1));
        rm1 = fmaxf(rm1, __shfl_xor_sync(0xffffffffu, rm1, 2));
        float nm0 = fmaxf(m0, rm0), nm1 = fmaxf(m1, rm1);
        float f0 = __expf(m0 - nm0), f1 = __expf(m1 - nm1);
        m0 = nm0; m1 = nm1;
        float p[8][4];
        float rs0 = 0.f, rs1 = 0.f;
        #pragma unroll
        for (int nt = 0; nt < 8; nt++) {
            p[nt][0] = __expf(s[nt][0] - nm0);
            p[nt][1] = __expf(s[nt][1] - nm0);
            p[nt][2] = __expf(s[nt][2] - nm1);
            p[nt][3] = __expf(s[nt][3] - nm1);
            rs0 += p[nt][0] + p[nt][1];
            rs1 += p[nt][2] + p[nt][3];
            o[nt][0] *= f0; o[nt][1] *= f0; o[nt][2] *= f1; o[nt][3] *= f1;
        }
        rs0 += __shfl_xor_sync(0xffffffffu, rs0, 1);
        rs0 += __shfl_xor_sync(0xffffffffu, rs0, 2);
        rs1 += __shfl_xor_sync(0xffffffffu, rs1, 1);
        rs1 += __shfl_xor_sync(0xffffffffu, rs1, 2);
        l0 = l0 * f0 + rs0;
        l1 = l1 * f1 + rs1;

        // O += P @ V : P fed straight from registers (C-layout == A-layout
        // under the sigma row permutation of V)
        #pragma unroll
        for (int ks = 0; ks < 8; ks++) {
            uint32_t a0 = f2tf(p[ks][0]);
            uint32_t a1 = f2tf(p[ks][2]);
            uint32_t a2 = f2tf(p[ks][1]);
            uint32_t a3 = f2tf(p[ks][3]);
            #pragma unroll
            for (int nt = 0; nt < 8; nt++) {
                uint32_t b0 = fu(Vs[(ks * 8 + t4) * 72 + nt * 8 + g]);
                uint32_t b1 = fu(Vs[(ks * 8 + t4 + 4) * 72 + nt * 8 + g]);
                mma8(o[nt], a0, a1, a2, a3, b0, b1);
            }
        }
        __syncthreads();   // done reading Ks/Vs before restaging

        if (kt < 6) {
            size_t so = base + (size_t)((kt + 2) * 64) * 64;
            for (int e = tid; e < 1024; e += 128) {
                int r = e >> 4, c4 = (e & 15) * 4;
                cpa16(Ks + r * 68 + c4, gKt + so + r * 64 + c4);
                cpa16(Vs + chmap(r) * 72 + c4, gVt + so + r * 64 + c4);
            }
        }
        CP_COMMIT();
    }

    // write O/l to g_xc (permuted channel layout)
    float i0 = 1.f / l0, i1 = 1.f / l1;
    int j0 = qt * 64 + qm + g, j1 = j0 + 8;
    int L0 = tok_to_L(branch, wloc, j0), L1 = tok_to_L(branch, wloc, j1);
    size_t d0 = ((size_t)(b * HW + L0)) * 256 + branch * 128 + head * 64;
    size_t d1 = ((size_t)(b * HW + L1)) * 256 + branch * 128 + head * 64;
    #pragma unroll
    for (int nt = 0; nt < 8; nt++) {
        int c = nt * 8 + 2 * t4;
        *(float2*)(g_xc + d0 + c) = make_float2(o[nt][0] * i0, o[nt][1] * i0);
        *(float2*)(g_xc + d1 + c) = make_float2(o[nt][2] * i1, o[nt][3] * i1);
    }
}

// ---------------------------------------------------------------------------
// 3) LePE: depthwise 3x3 on v (attention layout), += into g_xc (perm layout)
__global__ void lepe_kernel(const float* __restrict__ w1, const float* __restrict__ b1,
                            const float* __restrict__ w2, const float* __restrict__ b2) {
    __shared__ float swT[9][64];
    __shared__ float sb[64];
    int blk = blockIdx.x;               // 16384
    int pxg    = blk & 31;
    int win    = (blk >> 5) & 127;
    int head   = (blk >> 12) & 1;
    int branch = blk >> 13;
    const float* w    = branch ? w2 : w1;
    const float* bias = branch ? b2 : b1;
    int tid = threadIdx.x;
    for (int idx = tid; idx < 576; idx += 256) {
        int k = idx >> 6, c = idx & 63;
        swT[k][c] = w[(head + 2 * c) * 9 + k];
    }
    if (tid < 64) sb[tid] = bias[head + 2 * tid];
    __syncthreads();

    int c4 = (tid & 15) * 4;
    int px = pxg * 16 + (tid >> 4);
    int b = win >> 5, wloc = win & 31;
    int wshift = branch ? 7 : 2;
    int wsp = 1 << wshift, hsp = branch ? 4 : 128;
    int i = px >> wshift, jc = px & (wsp - 1);
    int slab = ((branch << 2) + b) * 32 + wloc;
    const float* vbase = gVt + ((size_t)(slab * 2 + head)) * 32768 + c4;

    float4 acc = *(const float4*)(sb + c4);
    #pragma unroll
    for (int t = 0; t < 9; t++) {
        int di = t / 3 - 1, dj = t % 3 - 1;
        int ii = i + di, jj = jc + dj;
        if (ii >= 0 && ii < hsp && jj >= 0 && jj < wsp) {
            float4 v  = *(const float4*)(vbase + (ii * wsp + jj) * 64);
            float4 wv = *(const float4*)(&swT[t][c4]);
            acc.x = fmaf(v.x, wv.x, acc.x);
            acc.y = fmaf(v.y, wv.y, acc.y);
            acc.z = fmaf(v.z, wv.z, acc.z);
            acc.w = fmaf(v.w, wv.w, acc.w);
        }
    }
    int L0 = branch ? ((wloc * 4 + i) * WWI + jc) : (i * WWI + wloc * 4 + jc);
    float* dst = g_xc + ((size_t)(b * HW + L0)) * 256 + branch * 128 + head * 64 + c4;
    float4 cur = *(float4*)dst;
    cur.x += acc.x; cur.y += acc.y; cur.z += acc.z; cur.w += acc.w;
    *(float4*)dst = cur;
}

// ---------------------------------------------------------------------------
// 4) Projection (tf32 tensor cores). grid (2,512): bn fastest -> A L2-reuse
__global__ void proj_tc_kernel(const float* __restrict__ Wp,
                               const float* __restrict__ bias,
                               float* __restrict__ out) {
    extern __shared__ float sh[];
    float* As = sh;                 // [128][20]
    float* Bs = sh + 128 * 20;      // [16][136]
    int bm = blockIdx.y, bn = blockIdx.x;
    int tid = threadIdx.x, wid = tid >> 5, lane = tid & 31;
    int g = lane >> 2, t4 = lane & 3;
    int wm = (wid >> 2) * 64, wn = (wid & 3) * 32;
    float acc[4][4][4];
    #pragma unroll
    for (int mt = 0; mt < 4; mt++)
        #pragma unroll
        for (int nt = 0; nt < 4; nt++)
            #pragma unroll
            for (int r = 0; r < 4; r++) acc[mt][nt][r] = 0.f;

    for (int k0 = 0; k0 < 256; k0 += 16) {
        { // A from g_xc (perm layout; k index IS the perm index)
            int m = tid >> 1, kb = (tid & 1) * 8;
            const float* a = g_xc + (size_t)(bm * 128 + m) * 256 + k0 + kb;
            float4 v0 = *(const float4*)a, v1 = *(const float4*)(a + 4);
            float* da = As + m * 20 + kb;
            da[0] = f2tff(v0.x); da[1] = f2tff(v0.y); da[2] = f2tff(v0.z); da[3] = f2tff(v0.w);
            da[4] = f2tff(v1.x); da[5] = f2tff(v1.y); da[6] = f2tff(v1.z); da[7] = f2tff(v1.w);
        }
        // B gather: Bs[k][n] = W[bn*128+n][ch(k0+k)]
        for (int idx = tid; idx < 2048; idx += 256) {
            int kk = idx & 15, n = idx >> 4;
            int kg = k0 + kk;
            int br = kg >> 7, p = kg & 127;
            int ch = br * 128 + (p >> 6) + 2 * (p & 63);
            Bs[kk * 136 + n] = f2tff(Wp[(size_t)(bn * 128 + n) * 256 + ch]);
        }
        __syncthreads();
        #pragma unroll
        for (int ks = 0; ks < 2; ks++) {
            uint32_t bf[4][2];
            #pragma unroll
            for (int nt = 0; nt < 4; nt++) {
                bf[nt][0] = fu(Bs[(ks * 8 + t4) * 136 + wn + nt * 8 + g]);
                bf[nt][1] = fu(Bs[(ks * 8 + t4 + 4) * 136 + wn + nt * 8 + g]);
            }
            #pragma unroll
            for (int mt = 0; mt < 4; mt++) {
                uint32_t a0 = fu(As[(wm + mt * 16 + g) * 20 + ks * 8 + t4]);
                uint32_t a1 = fu(As[(wm + mt * 16 + g + 8) * 20 + ks * 8 + t4]);
                uint32_t a2 = fu(As[(wm + mt * 16 + g) * 20 + ks * 8 + t4 + 4]);
                uint32_t a3 = fu(As[(wm + mt * 16 + g + 8) * 20 + ks * 8 + t4 + 4]);
                #pragma unroll
                for (int nt = 0; nt < 4; nt++)
                    mma8(acc[mt][nt], a0, a1, a2, a3, bf[nt][0], bf[nt][1]);
            }
        }
        __syncthreads();
    }
    #pragma unroll
    for (int mt = 0; mt < 4; mt++) {
        int r = bm * 128 + wm + mt * 16 + g;
        int b = r >> 14, t = r & 16383;
        #pragma unroll
        for (int nt = 0; nt < 4; nt++) {
            int oc = bn * 128 + wn + nt * 8 + 2 * t4;
            float b0 = bias[oc], b1 = bias[oc + 1];
            out[((size_t)(b * 256 + oc)) * HW + t]         = acc[mt][nt][0] + b0;
            out[((size_t)(b * 256 + oc + 1)) * HW + t]     = acc[mt][nt][1] + b1;
            out[((size_t)(b * 256 + oc)) * HW + t + 8]     = acc[mt][nt][2] + b0;
            out[((size_t)(b * 256 + oc + 1)) * HW + t + 8] = acc[mt][nt][3] + b1;
        }
    }
}

// ---------------------------------------------------------------------------
extern "C" void kernel_launch(void* const* d_in, const int* in_sizes, int n_in,
                              void* d_out, int out_size) {
    const float* x       = (const float*)d_in[0];
    const float* ln_g    = (const float*)d_in[1];
    const float* ln_b    = (const float*)d_in[2];
    const float* w_qkv   = (const float*)d_in[3];
    const float* lepe_w1 = (const float*)d_in[4];
    const float* lepe_b1 = (const float*)d_in[5];
    const float* lepe_w2 = (const float*)d_in[6];
    const float* lepe_b2 = (const float*)d_in[7];
    const float* proj_w  = (const float*)d_in[8];
    const float* proj_b  = (const float*)d_in[9];
    float* out = (float*)d_out;

    const int qkv_smem  = 128 * 132 * 4;                   // 67584 B (C staging)
    const int attn_smem = (2 * 64 * 68 + 2 * 64 * 72) * 4; // 71680 B
    const int proj_smem = (128 * 20 + 16 * 136) * 4;       // 18944 B
    cudaFuncSetAttribute(qkv_tc_kernel,  cudaFuncAttributeMaxDynamicSharedMemorySize, qkv_smem);
    cudaFuncSetAttribute(attn_tc_kernel, cudaFuncAttributeMaxDynamicSharedMemorySize, attn_smem);

    qkv_tc_kernel<<<dim3(6, 512), 256, qkv_smem>>>(x, ln_g, ln_b, w_qkv);
    attn_tc_kernel<<<4096, 128, attn_smem>>>();
    lepe_kernel<<<16384, 256>>>(lepe_w1, lepe_b1, lepe_w2, lepe_b2);
    proj_tc_kernel<<<dim3(2, 512), 256, proj_smem>>>(proj_w, proj_b, out);
}

// round 12
// speedup vs baseline: 1.1903x; 1.1903x over previous
#include <cuda_runtime.h>
#include <cstdint>
#include <cstddef>

// Problem constants
#define BB 4
#define CC 256
#define HH 128
#define WWI 128
#define HW 16384          // H*W
#define NTOK 65536        // B*HW
#define SCALE_F 0.08838834764831843f   // (256/2)^-0.5
#define EPS_F 1e-4f

// Scratch (device globals — no allocations allowed)
__device__ float g_xp[(size_t)NTOK * CC];                 // LN output, token-major
__device__ float g_xc[(size_t)NTOK * CC];                 // attn+lepe out (PERM ch: branch*128+head*64+c)
// attention-layout tensors: [(branch*4+b)*32+wloc][head][j:512][c:64], tf32-rounded
__device__ float gQt[(size_t)256 * 2 * 512 * 64];         // pre-scaled by SCALE
__device__ float gKt[(size_t)256 * 2 * 512 * 64];
__device__ float gVt[(size_t)256 * 2 * 512 * 64];
__device__ float g_Wt[256 * 256];                         // proj W: [k_perm][oc], tf32-rounded

// ---------------------------------------------------------------------------
__device__ __forceinline__ uint32_t f2tf(float f) {
    uint32_t u; asm("cvt.rna.tf32.f32 %0, %1;" : "=r"(u) : "f"(f)); return u;
}
__device__ __forceinline__ float f2tff(float f) { return __uint_as_float(f2tf(f)); }
__device__ __forceinline__ uint32_t fu(float f) { return __float_as_uint(f); }

__device__ __forceinline__ void mma8(float* d,
    uint32_t a0, uint32_t a1, uint32_t a2, uint32_t a3, uint32_t b0, uint32_t b1) {
    asm volatile(
        "mma.sync.aligned.m16n8k8.row.col.f32.tf32.tf32.f32 "
        "{%0,%1,%2,%3},{%4,%5,%6,%7},{%8,%9},{%0,%1,%2,%3};\n"
        : "+f"(d[0]), "+f"(d[1]), "+f"(d[2]), "+f"(d[3])
        : "r"(a0), "r"(a1), "r"(a2), "r"(a3), "r"(b0), "r"(b1));
}

__device__ __forceinline__ void cpa16(void* dst, const void* src) {
    uint32_t d = (uint32_t)__cvta_generic_to_shared(dst);
    asm volatile("cp.async.cg.shared.global [%0], [%1], 16;\n" :: "r"(d), "l"(src));
}
#define CP_COMMIT() asm volatile("cp.async.commit_group;\n" ::: "memory")
#define CP_WAIT1()  asm volatile("cp.async.wait_group 1;\n" ::: "memory")
#define CP_WAIT0()  asm volatile("cp.async.wait_group 0;\n" ::: "memory")

__device__ __forceinline__ int tok_to_L(int branch, int wloc, int j) {
    if (branch == 0) { int hs = j >> 2, ws = j & 3;    return hs * WWI + wloc * 4 + ws; }
    else             { int hs = j >> 7, ws = j & 127;  return (wloc * 4 + hs) * WWI + ws; }
}

// ---------------------------------------------------------------------------
// 0) Pre-permute proj W: g_Wt[p][o] = tf32(W[o][ch(p)])
//    perm index p -> original channel: br=p>>7, q=p&127, ch=br*128+(q>>6)+2*(q&63)
__global__ void wperm_kernel(const float* __restrict__ Wp) {
    int p = blockIdx.x, o = threadIdx.x;
    int br = p >> 7, q = p & 127;
    int ch = br * 128 + (q >> 6) + 2 * (q & 63);
    g_Wt[p * 256 + o] = f2tff(Wp[o * 256 + ch]);
}

// ---------------------------------------------------------------------------
// 1) LayerNorm: x [B,C,H,W] -> g_xp [B*HW, C]
__global__ void ln_kernel(const float* __restrict__ x,
                          const float* __restrict__ gam,
                          const float* __restrict__ bet) {
    __shared__ float tile[CC][33];
    __shared__ float smu[32], srs[32];
    int blk = blockIdx.x;            // 2048
    int b = blk >> 9;
    int t0 = (blk & 511) * 32;
    int tid = threadIdx.x;
    int tt = tid & 31, cc8 = tid >> 5;
    #pragma unroll
    for (int c0 = 0; c0 < CC; c0 += 8)
        tile[c0 + cc8][tt] = x[((size_t)b * CC + c0 + cc8) * HW + t0 + tt];
    __syncthreads();
    int warp = tid >> 5, lane = tid & 31;
    for (int u = 0; u < 4; u++) {
        int tok = warp * 4 + u;
        float s = 0.f, s2 = 0.f;
        #pragma unroll
        for (int c = lane; c < CC; c += 32) { float v = tile[c][tok]; s += v; s2 += v * v; }
        #pragma unroll
        for (int off = 16; off > 0; off >>= 1) {
            s  += __shfl_xor_sync(0xffffffffu, s,  off);
            s2 += __shfl_xor_sync(0xffffffffu, s2, off);
        }
        if (lane == 0) {
            float mu = s * (1.f / CC);
            smu[tok] = mu;
            srs[tok] = rsqrtf(s2 * (1.f / CC) - mu * mu + EPS_F);
        }
    }
    __syncthreads();
    for (int e = tid; e < 32 * CC; e += 256) {
        int tok = e >> 8, c = e & 255;
        g_xp[((size_t)(b * HW + t0 + tok)) * CC + c] =
            (tile[c][tok] - smu[tok]) * srs[tok] * gam[c] + bet[c];
    }
}

// ---------------------------------------------------------------------------
// 2) QKV GEMM (tf32 tensor cores). grid (6,512): bn fastest -> A tile L2-reused
__global__ void qkv_tc_kernel(const float* __restrict__ Bmat) {
    extern __shared__ float sh[];
    float* As = sh;                 // [128][20]
    float* Bs = sh + 128 * 20;      // [16][136]
    int bm = blockIdx.y, bn = blockIdx.x;
    int tid = threadIdx.x, wid = tid >> 5, lane = tid & 31;
    int g = lane >> 2, t4 = lane & 3;
    int wm = (wid >> 2) * 64, wn = (wid & 3) * 32;
    float acc[4][4][4];
    #pragma unroll
    for (int mt = 0; mt < 4; mt++)
        #pragma unroll
        for (int nt = 0; nt < 4; nt++)
            #pragma unroll
            for (int r = 0; r < 4; r++) acc[mt][nt][r] = 0.f;

    for (int k0 = 0; k0 < 256; k0 += 16) {
        { // load A 128x16 (cvt to tf32)
            int m = tid >> 1, kb = (tid & 1) * 8;
            const float* a = g_xp + (size_t)(bm * 128 + m) * 256 + k0 + kb;
            float4 v0 = *(const float4*)a, v1 = *(const float4*)(a + 4);
            float* da = As + m * 20 + kb;
            da[0] = f2tff(v0.x); da[1] = f2tff(v0.y); da[2] = f2tff(v0.z); da[3] = f2tff(v0.w);
            da[4] = f2tff(v1.x); da[5] = f2tff(v1.y); da[6] = f2tff(v1.z); da[7] = f2tff(v1.w);
        }
        { // load B 16x128
            int kr = tid >> 5, n4 = (tid & 31) * 4;
            #pragma unroll
            for (int p = 0; p < 2; p++) {
                float4 w = *(const float4*)(Bmat + (size_t)(k0 + kr + p * 8) * 768 + bn * 128 + n4);
                float* db = Bs + (kr + p * 8) * 136 + n4;
                db[0] = f2tff(w.x); db[1] = f2tff(w.y); db[2] = f2tff(w.z); db[3] = f2tff(w.w);
            }
        }
        __syncthreads();
        #pragma unroll
        for (int ks = 0; ks < 2; ks++) {
            uint32_t bf[4][2];
            #pragma unroll
            for (int nt = 0; nt < 4; nt++) {
                bf[nt][0] = fu(Bs[(ks * 8 + t4) * 136 + wn + nt * 8 + g]);
                bf[nt][1] = fu(Bs[(ks * 8 + t4 + 4) * 136 + wn + nt * 8 + g]);
            }
            #pragma unroll
            for (int mt = 0; mt < 4; mt++) {
                uint32_t a0 = fu(As[(wm + mt * 16 + g) * 20 + ks * 8 + t4]);
                uint32_t a1 = fu(As[(wm + mt * 16 + g + 8) * 20 + ks * 8 + t4]);
                uint32_t a2 = fu(As[(wm + mt * 16 + g) * 20 + ks * 8 + t4 + 4]);
                uint32_t a3 = fu(As[(wm + mt * 16 + g + 8) * 20 + ks * 8 + t4 + 4]);
                #pragma unroll
                for (int nt = 0; nt < 4; nt++)
                    mma8(acc[mt][nt], a0, a1, a2, a3, bf[nt][0], bf[nt][1]);
            }
        }
        __syncthreads();
    }
    // stage C to smem
    float* Cs = sh;  // [128][132]
    #pragma unroll
    for (int mt = 0; mt < 4; mt++)
        #pragma unroll
        for (int nt = 0; nt < 4; nt++) {
            int r = wm + mt * 16 + g, cl = wn + nt * 8 + 2 * t4;
            Cs[r * 132 + cl]           = acc[mt][nt][0];
            Cs[r * 132 + cl + 1]       = acc[mt][nt][1];
            Cs[(r + 8) * 132 + cl]     = acc[mt][nt][2];
            Cs[(r + 8) * 132 + cl + 1] = acc[mt][nt][3];
        }
    __syncthreads();
    int qkvt = bn >> 1, branch = bn & 1;
    float* dst = (qkvt == 0) ? gQt : ((qkvt == 1) ? gKt : gVt);
    float mul = (qkvt == 0) ? SCALE_F : 1.f;
    for (int e = tid; e < 4096; e += 256) {
        int tl = e >> 5, h = (e >> 4) & 1, c4 = (e & 15) * 4;
        int mg = bm * 128 + tl, b = mg >> 14, L = mg & 16383;
        int row = L >> 7, colL = L & 127;
        int wloc, j;
        if (branch == 0) { wloc = colL >> 2; j = row * 4 + (colL & 3); }
        else             { wloc = row >> 2;  j = ((row & 3) << 7) + colL; }
        int slab = ((branch << 2) + b) * 32 + wloc;
        size_t off = (((size_t)(slab * 2 + h)) * 512 + j) * 64 + c4;
        const float* cs = Cs + tl * 132 + h;
        float4 o;
        o.x = f2tff(cs[2 * (c4 + 0)] * mul);
        o.y = f2tff(cs[2 * (c4 + 1)] * mul);
        o.z = f2tff(cs[2 * (c4 + 2)] * mul);
        o.w = f2tff(cs[2 * (c4 + 3)] * mul);
        *(float4*)(dst + off) = o;
    }
}

// ---------------------------------------------------------------------------
// 3) Flash attention (tf32 tensor cores). Block = 128 threads (4 warps),
//    Q fragments in registers; cp.async double-buffered K/V staging.
__global__ void __launch_bounds__(128) attn_tc_kernel() {
    extern __shared__ float sh[];
    float* KsA = sh;                 // [2][64*68]  (K tile; reused for P)
    float* VsA = sh + 2 * 4352;      // [2][64*72]

    int bid = blockIdx.x;
    int qt = bid & 7, head = (bid >> 3) & 1, win = (bid >> 4) & 127, branch = bid >> 11;
    int b = win >> 5, wloc = win & 31;
    int slab = ((branch << 2) + b) * 32 + wloc;
    size_t base = ((size_t)(slab * 2 + head)) * 512 * 64;

    int tid = threadIdx.x, wid = tid >> 5, lane = tid & 31;
    int g = lane >> 2, t4 = lane & 3;
    int qm = wid * 16;

    // -- stage Q tile into KsA[0], then extract fragments to registers
    for (int e = tid; e < 1024; e += 128) {
        int r = e >> 4, c4 = (e & 15) * 4;
        cpa16(KsA + r * 68 + c4, gQt + base + (size_t)(qt * 64 + r) * 64 + c4);
    }
    CP_COMMIT(); CP_WAIT0();
    __syncthreads();
    uint32_t qf[8][4];
    #pragma unroll
    for (int ks = 0; ks < 8; ks++) {
        qf[ks][0] = fu(KsA[(qm + g) * 68 + ks * 8 + t4]);
        qf[ks][1] = fu(KsA[(qm + g + 8) * 68 + ks * 8 + t4]);
        qf[ks][2] = fu(KsA[(qm + g) * 68 + ks * 8 + t4 + 4]);
        qf[ks][3] = fu(KsA[(qm + g + 8) * 68 + ks * 8 + t4 + 4]);
    }
    __syncthreads();

    // -- prologue: stage kt=0 and kt=1
    #pragma unroll 1
    for (int pkt = 0; pkt < 2; pkt++) {
        float* kd = KsA + pkt * 4352;
        float* vd = VsA + pkt * 4608;
        size_t so = base + (size_t)(pkt * 64) * 64;
        for (int e = tid; e < 1024; e += 128) {
            int r = e >> 4, c4 = (e & 15) * 4;
            cpa16(kd + r * 68 + c4, gKt + so + r * 64 + c4);
            cpa16(vd + r * 72 + c4, gVt + so + r * 64 + c4);
        }
        CP_COMMIT();
    }

    float o[8][4];
    #pragma unroll
    for (int nt = 0; nt < 8; nt++)
        #pragma unroll
        for (int r = 0; r < 4; r++) o[nt][r] = 0.f;
    float m0 = -1e30f, m1 = -1e30f, l0 = 0.f, l1 = 0.f;

    #pragma unroll 1
    for (int kt = 0; kt < 8; kt++) {
        int cur = kt & 1;
        float* Ks = KsA + cur * 4352;
        float* Vs = VsA + cur * 4608;
        CP_WAIT1();
        __syncthreads();

        // S = Q K^T
        float s[8][4];
        #pragma unroll
        for (int nt = 0; nt < 8; nt++)
            #pragma unroll
            for (int r = 0; r < 4; r++) s[nt][r] = 0.f;
        #pragma unroll
        for (int ks = 0; ks < 8; ks++) {
            #pragma unroll
            for (int nt = 0; nt < 8; nt++) {
                uint32_t b0 = fu(Ks[(nt * 8 + g) * 68 + ks * 8 + t4]);
                uint32_t b1 = fu(Ks[(nt * 8 + g) * 68 + ks * 8 + t4 + 4]);
                mma8(s[nt], qf[ks][0], qf[ks][1], qf[ks][2], qf[ks][3], b0, b1);
            }
        }
        __syncthreads();   // all warps done reading Ks before P overwrite

        // online softmax; thread owns rows (qm+g) regs{0,1}, (qm+g+8) regs{2,3}
        float rm0 = -1e30f, rm1 = -1e30f;
        #pragma unroll
        for (int nt = 0; nt < 8; nt++) {
            rm0 = fmaxf(rm0, fmaxf(s[nt][0], s[nt][1]));
            rm1 = fmaxf(rm1, fmaxf(s[nt][2], s[nt][3]));
        }
        rm0 = fmaxf(rm0, __shfl_xor_sync(0xffffffffu, rm0, 1));
        rm0 = fmaxf(rm0, __shfl_xor_sync(0xffffffffu, rm0, 2));
        rm1 = fmaxf(rm1, __shfl_xor_sync(0xffffffffu, rm1, 1));
        rm1 = fmaxf(rm1, __shfl_xor_sync(0xffffffffu, rm1, 2));
        float nm0 = fmaxf(m0, rm0), nm1 = fmaxf(m1, rm1);
        float f0 = __expf(m0 - nm0), f1 = __expf(m1 - nm1);
        m0 = nm0; m1 = nm1;
        float rs0 = 0.f, rs1 = 0.f;
        #pragma unroll
        for (int nt = 0; nt < 8; nt++) {
            float p0 = __expf(s[nt][0] - nm0), p1 = __expf(s[nt][1] - nm0);
            float p2 = __expf(s[nt][2] - nm1), p3 = __expf(s[nt][3] - nm1);
            rs0 += p0 + p1; rs1 += p2 + p3;
            float* pp = Ks + (qm + g) * 68 + nt * 8 + 2 * t4;
            pp[0] = f2tff(p0); pp[1] = f2tff(p1);
            float* pq = Ks + (qm + g + 8) * 68 + nt * 8 + 2 * t4;
            pq[0] = f2tff(p2); pq[1] = f2tff(p3);
            o[nt][0] *= f0; o[nt][1] *= f0; o[nt][2] *= f1; o[nt][3] *= f1;
        }
        rs0 += __shfl_xor_sync(0xffffffffu, rs0, 1);
        rs0 += __shfl_xor_sync(0xffffffffu, rs0, 2);
        rs1 += __shfl_xor_sync(0xffffffffu, rs1, 1);
        rs1 += __shfl_xor_sync(0xffffffffu, rs1, 2);
        l0 = l0 * f0 + rs0;
        l1 = l1 * f1 + rs1;
        __syncwarp();      // P rows are warp-private

        // O += P @ V
        #pragma unroll
        for (int ks = 0; ks < 8; ks++) {
            uint32_t a0 = fu(Ks[(qm + g) * 68 + ks * 8 + t4]);
            uint32_t a1 = fu(Ks[(qm + g + 8) * 68 + ks * 8 + t4]);
            uint32_t a2 = fu(Ks[(qm + g) * 68 + ks * 8 + t4 + 4]);
            uint32_t a3 = fu(Ks[(qm + g + 8) * 68 + ks * 8 + t4 + 4]);
            #pragma unroll
            for (int nt = 0; nt < 8; nt++) {
                uint32_t b0 = fu(Vs[(ks * 8 + t4) * 72 + nt * 8 + g]);
                uint32_t b1 = fu(Vs[(ks * 8 + t4 + 4) * 72 + nt * 8 + g]);
                mma8(o[nt], a0, a1, a2, a3, b0, b1);
            }
        }
        __syncthreads();   // done with this buffer before restaging it

        if (kt < 6) {      // stage kt+2 into this buffer
            float* kd = Ks;
            float* vd = Vs;
            size_t so = base + (size_t)((kt + 2) * 64) * 64;
            for (int e = tid; e < 1024; e += 128) {
                int r = e >> 4, c4 = (e & 15) * 4;
                cpa16(kd + r * 68 + c4, gKt + so + r * 64 + c4);
                cpa16(vd + r * 72 + c4, gVt + so + r * 64 + c4);
            }
        }
        CP_COMMIT();
    }

    // write O/l to g_xc (permuted channel layout)
    float i0 = 1.f / l0, i1 = 1.f / l1;
    int j0 = qt * 64 + qm + g, j1 = j0 + 8;
    int L0 = tok_to_L(branch, wloc, j0), L1 = tok_to_L(branch, wloc, j1);
    size_t d0 = ((size_t)(b * HW + L0)) * 256 + branch * 128 + head * 64;
    size_t d1 = ((size_t)(b * HW + L1)) * 256 + branch * 128 + head * 64;
    #pragma unroll
    for (int nt = 0; nt < 8; nt++) {
        int c = nt * 8 + 2 * t4;
        *(float2*)(g_xc + d0 + c) = make_float2(o[nt][0] * i0, o[nt][1] * i0);
        *(float2*)(g_xc + d1 + c) = make_float2(o[nt][2] * i1, o[nt][3] * i1);
    }
}

// ---------------------------------------------------------------------------
// 4) LePE: depthwise 3x3 on v (attention layout), += into g_xc (perm layout)
__global__ void lepe_kernel(const float* __restrict__ w1, const float* __restrict__ b1,
                            const float* __restrict__ w2, const float* __restrict__ b2) {
    __shared__ float swT[9][64];
    __shared__ float sb[64];
    int blk = blockIdx.x;               // 16384
    int pxg    = blk & 31;
    int win    = (blk >> 5) & 127;
    int head   = (blk >> 12) & 1;
    int branch = blk >> 13;
    const float* w    = branch ? w2 : w1;
    const float* bias = branch ? b2 : b1;
    int tid = threadIdx.x;
    for (int idx = tid; idx < 576; idx += 256) {
        int k = idx >> 6, c = idx & 63;
        swT[k][c] = w[(head + 2 * c) * 9 + k];
    }
    if (tid < 64) sb[tid] = bias[head + 2 * tid];
    __syncthreads();

    int c4 = (tid & 15) * 4;
    int px = pxg * 16 + (tid >> 4);
    int b = win >> 5, wloc = win & 31;
    int wshift = branch ? 7 : 2;
    int wsp = 1 << wshift, hsp = branch ? 4 : 128;
    int i = px >> wshift, jc = px & (wsp - 1);
    int slab = ((branch << 2) + b) * 32 + wloc;
    const float* vbase = gVt + ((size_t)(slab * 2 + head)) * 32768 + c4;

    float4 acc = *(const float4*)(sb + c4);
    #pragma unroll
    for (int t = 0; t < 9; t++) {
        int di = t / 3 - 1, dj = t % 3 - 1;
        int ii = i + di, jj = jc + dj;
        if (ii >= 0 && ii < hsp && jj >= 0 && jj < wsp) {
            float4 v  = *(const float4*)(vbase + (ii * wsp + jj) * 64);
            float4 wv = *(const float4*)(&swT[t][c4]);
            acc.x = fmaf(v.x, wv.x, acc.x);
            acc.y = fmaf(v.y, wv.y, acc.y);
            acc.z = fmaf(v.z, wv.z, acc.z);
            acc.w = fmaf(v.w, wv.w, acc.w);
        }
    }
    int L0 = branch ? ((wloc * 4 + i) * WWI + jc) : (i * WWI + wloc * 4 + jc);
    float* dst = g_xc + ((size_t)(b * HW + L0)) * 256 + branch * 128 + head * 64 + c4;
    float4 cur = *(float4*)dst;
    cur.x += acc.x; cur.y += acc.y; cur.z += acc.z; cur.w += acc.w;
    *(float4*)dst = cur;
}

// ---------------------------------------------------------------------------
// 5) Projection (tf32 tensor cores). grid (2,512): bn fastest -> A L2-reuse.
//    B side reads PRE-PERMUTED g_Wt with coalesced float4 (was scalar gather).
__global__ void proj_tc_kernel(const float* __restrict__ bias,
                               float* __restrict__ out) {
    extern __shared__ float sh[];
    float* As = sh;                 // [128][20]
    float* Bs = sh + 128 * 20;      // [16][136]
    int bm = blockIdx.y, bn = blockIdx.x;
    int tid = threadIdx.x, wid = tid >> 5, lane = tid & 31;
    int g = lane >> 2, t4 = lane & 3;
    int wm = (wid >> 2) * 64, wn = (wid & 3) * 32;
    float acc[4][4][4];
    #pragma unroll
    for (int mt = 0; mt < 4; mt++)
        #pragma unroll
        for (int nt = 0; nt < 4; nt++)
            #pragma unroll
            for (int r = 0; r < 4; r++) acc[mt][nt][r] = 0.f;

    for (int k0 = 0; k0 < 256; k0 += 16) {
        { // A from g_xc (perm layout; k index IS the perm index)
            int m = tid >> 1, kb = (tid & 1) * 8;
            const float* a = g_xc + (size_t)(bm * 128 + m) * 256 + k0 + kb;
            float4 v0 = *(const float4*)a, v1 = *(const float4*)(a + 4);
            float* da = As + m * 20 + kb;
            da[0] = f2tff(v0.x); da[1] = f2tff(v0.y); da[2] = f2tff(v0.z); da[3] = f2tff(v0.w);
            da[4] = f2tff(v1.x); da[5] = f2tff(v1.y); da[6] = f2tff(v1.z); da[7] = f2tff(v1.w);
        }
        { // B from g_Wt (pre-permuted, pre-rounded): coalesced float4
            int kr = tid >> 5, n4 = (tid & 31) * 4;
            #pragma unroll
            for (int p = 0; p < 2; p++) {
                float4 w = *(const float4*)(g_Wt + (size_t)(k0 + kr + p * 8) * 256 + bn * 128 + n4);
                *(float4*)(&Bs[(kr + p * 8) * 136 + n4]) = w;
            }
        }
        __syncthreads();
        #pragma unroll
        for (int ks = 0; ks < 2; ks++) {
            uint32_t bf[4][2];
            #pragma unroll
            for (int nt = 0; nt < 4; nt++) {
                bf[nt][0] = fu(Bs[(ks * 8 + t4) * 136 + wn + nt * 8 + g]);
                bf[nt][1] = fu(Bs[(ks * 8 + t4 + 4) * 136 + wn + nt * 8 + g]);
            }
            #pragma unroll
            for (int mt = 0; mt < 4; mt++) {
                uint32_t a0 = fu(As[(wm + mt * 16 + g) * 20 + ks * 8 + t4]);
                uint32_t a1 = fu(As[(wm + mt * 16 + g + 8) * 20 + ks * 8 + t4]);
                uint32_t a2 = fu(As[(wm + mt * 16 + g) * 20 + ks * 8 + t4 + 4]);
                uint32_t a3 = fu(As[(wm + mt * 16 + g + 8) * 20 + ks * 8 + t4 + 4]);
                #pragma unroll
                for (int nt = 0; nt < 4; nt++)
                    mma8(acc[mt][nt], a0, a1, a2, a3, bf[nt][0], bf[nt][1]);
            }
        }
        __syncthreads();
    }
    #pragma unroll
    for (int mt = 0; mt < 4; mt++) {
        int r = bm * 128 + wm + mt * 16 + g;
        int b = r >> 14, t = r & 16383;
        #pragma unroll
        for (int nt = 0; nt < 4; nt++) {
            int oc = bn * 128 + wn + nt * 8 + 2 * t4;
            float b0 = bias[oc], b1 = bias[oc + 1];
            out[((size_t)(b * 256 + oc)) * HW + t]         = acc[mt][nt][0] + b0;
            out[((size_t)(b * 256 + oc + 1)) * HW + t]     = acc[mt][nt][1] + b1;
            out[((size_t)(b * 256 + oc)) * HW + t + 8]     = acc[mt][nt][2] + b0;
            out[((size_t)(b * 256 + oc + 1)) * HW + t + 8] = acc[mt][nt][3] + b1;
        }
    }
}

// ---------------------------------------------------------------------------
extern "C" void kernel_launch(void* const* d_in, const int* in_sizes, int n_in,
                              void* d_out, int out_size) {
    const float* x       = (const float*)d_in[0];
    const float* ln_g    = (const float*)d_in[1];
    const float* ln_b    = (const float*)d_in[2];
    const float* w_qkv   = (const float*)d_in[3];
    const float* lepe_w1 = (const float*)d_in[4];
    const float* lepe_b1 = (const float*)d_in[5];
    const float* lepe_w2 = (const float*)d_in[6];
    const float* lepe_b2 = (const float*)d_in[7];
    const float* proj_w  = (const float*)d_in[8];
    const float* proj_b  = (const float*)d_in[9];
    float* out = (float*)d_out;

    const int qkv_smem  = 128 * 132 * 4;                   // 67584 B (C staging)
    const int attn_smem = (2 * 64 * 68 + 2 * 64 * 72) * 4; // 71680 B
    const int proj_smem = (128 * 20 + 16 * 136) * 4;       // 18944 B
    cudaFuncSetAttribute(qkv_tc_kernel,  cudaFuncAttributeMaxDynamicSharedMemorySize, qkv_smem);
    cudaFuncSetAttribute(attn_tc_kernel, cudaFuncAttributeMaxDynamicSharedMemorySize, attn_smem);

    wperm_kernel<<<256, 256>>>(proj_w);
    ln_kernel<<<2048, 256>>>(x, ln_g, ln_b);
    qkv_tc_kernel<<<dim3(6, 512), 256, qkv_smem>>>(w_qkv);
    attn_tc_kernel<<<4096, 128, attn_smem>>>();
    lepe_kernel<<<16384, 256>>>(lepe_w1, lepe_b1, lepe_w2, lepe_b2);
    proj_tc_kernel<<<dim3(2, 512), 256, proj_smem>>>(proj_b, out);
}